// round 2
// baseline (speedup 1.0000x reference)
#include <cuda_runtime.h>

#define BB 2
#define LL 512
#define DD 128
#define TI 16
#define TJ 64
#define TJP 65

__device__ float g_sW[BB*LL*DD];
__device__ float g_hU[BB*LL*DD];
__device__ float g_scores[(size_t)BB*LL*LL];

__device__ __forceinline__ float tanh_apx(float x){
    float y; asm("tanh.approx.f32 %0, %1;" : "=f"(y) : "f"(x)); return y;
}

// ---------------- Kernel 0: sW = s@W, hU = h@U ----------------
__global__ void __launch_bounds__(128) proj_kernel(const float* __restrict__ s,
                                                   const float* __restrict__ h,
                                                   const float* __restrict__ W,
                                                   const float* __restrict__ U){
    __shared__ float row_s[DD];
    int row   = blockIdx.x;      // 0..B*L-1
    int which = blockIdx.y;      // 0 -> sW, 1 -> hU
    const float* src = which ? h : s;
    const float* M   = which ? U : W;
    float* dst       = which ? g_hU : g_sW;
    int d = threadIdx.x;
    row_s[d] = src[row*DD + d];
    __syncthreads();
    float a0=0.f, a1=0.f, a2=0.f, a3=0.f;
#pragma unroll
    for (int k = 0; k < DD; k += 4){
        a0 = fmaf(row_s[k+0], M[(k+0)*DD + d], a0);
        a1 = fmaf(row_s[k+1], M[(k+1)*DD + d], a1);
        a2 = fmaf(row_s[k+2], M[(k+2)*DD + d], a2);
        a3 = fmaf(row_s[k+3], M[(k+3)*DD + d], a3);
    }
    dst[row*DD + d] = (a0 + a1) + (a2 + a3);
}

// ---------------- Kernel 1: scores[b,i,j] = sum_d tanh(sW[i,d]+hU[j,d])*v[d] ----------------
__global__ void __launch_bounds__(256) scores_kernel(const float* __restrict__ v){
    __shared__ float hU_t[DD][TJP];     // transposed [d][j], pad 65 -> conflict free
    __shared__ float sW_s[TI][DD];
    __shared__ float v_s[DD];

    int b  = blockIdx.z;
    int i0 = blockIdx.y * TI;
    int j0 = blockIdx.x * TJ;
    int t  = threadIdx.x;

    if (t < DD) v_s[t] = v[t];

    // load sW tile (16x128) as float4, coalesced
    {
        const float4* src = (const float4*)(g_sW + (size_t)(b*LL + i0)*DD);
#pragma unroll
        for (int q = 0; q < 2; q++){
            int lin = t + q*256;         // float4 index over 512
            int i  = lin >> 5;
            int dv = lin & 31;
            ((float4*)&sW_s[i][0])[dv] = src[i*32 + dv];
        }
    }
    // load hU tile (64x128) transposed; scalar, conflict-free on pad-65
    {
        const float* src = g_hU + (size_t)(b*LL + j0)*DD;
#pragma unroll
        for (int q = 0; q < 32; q++){
            int lin = t + q*256;
            int j = lin >> 7;
            int d = lin & 127;
            hU_t[d][j] = src[j*DD + d];
        }
    }
    __syncthreads();

    int jl = t & 63;          // j lane within tile
    int g  = t >> 6;          // 0..3  -> i group
    int ib = g * 4;           // local i base (4 i's per thread)

    float acc0=0.f, acc1=0.f, acc2=0.f, acc3=0.f;
    const float4* vv4 = (const float4*)v_s;
    const float4* w0p = (const float4*)&sW_s[ib+0][0];
    const float4* w1p = (const float4*)&sW_s[ib+1][0];
    const float4* w2p = (const float4*)&sW_s[ib+2][0];
    const float4* w3p = (const float4*)&sW_s[ib+3][0];

#pragma unroll 8
    for (int d4 = 0; d4 < 32; ++d4){
        float4 vv = vv4[d4];
        float4 w0 = w0p[d4];
        float4 w1 = w1p[d4];
        float4 w2 = w2p[d4];
        float4 w3 = w3p[d4];
        {
            float hu = hU_t[4*d4+0][jl];
            acc0 = fmaf(tanh_apx(w0.x + hu), vv.x, acc0);
            acc1 = fmaf(tanh_apx(w1.x + hu), vv.x, acc1);
            acc2 = fmaf(tanh_apx(w2.x + hu), vv.x, acc2);
            acc3 = fmaf(tanh_apx(w3.x + hu), vv.x, acc3);
        }
        {
            float hu = hU_t[4*d4+1][jl];
            acc0 = fmaf(tanh_apx(w0.y + hu), vv.y, acc0);
            acc1 = fmaf(tanh_apx(w1.y + hu), vv.y, acc1);
            acc2 = fmaf(tanh_apx(w2.y + hu), vv.y, acc2);
            acc3 = fmaf(tanh_apx(w3.y + hu), vv.y, acc3);
        }
        {
            float hu = hU_t[4*d4+2][jl];
            acc0 = fmaf(tanh_apx(w0.z + hu), vv.z, acc0);
            acc1 = fmaf(tanh_apx(w1.z + hu), vv.z, acc1);
            acc2 = fmaf(tanh_apx(w2.z + hu), vv.z, acc2);
            acc3 = fmaf(tanh_apx(w3.z + hu), vv.z, acc3);
        }
        {
            float hu = hU_t[4*d4+3][jl];
            acc0 = fmaf(tanh_apx(w0.w + hu), vv.w, acc0);
            acc1 = fmaf(tanh_apx(w1.w + hu), vv.w, acc1);
            acc2 = fmaf(tanh_apx(w2.w + hu), vv.w, acc2);
            acc3 = fmaf(tanh_apx(w3.w + hu), vv.w, acc3);
        }
    }

    float* dst = g_scores + ((size_t)(b*LL + i0 + ib))*LL + j0 + jl;
    dst[0*LL] = acc0;
    dst[1*LL] = acc1;
    dst[2*LL] = acc2;
    dst[3*LL] = acc3;
}

// ---------------- Kernel 2: softmax over j + out = attn @ h ----------------
__global__ void __launch_bounds__(256) softmax_out_kernel(const float* __restrict__ h,
                                                          float* __restrict__ out){
    __shared__ float p_s[16][LL];   // 32KB
    __shared__ float inv_s[16];

    int b  = blockIdx.y;
    int i0 = blockIdx.x * 16;
    int t  = threadIdx.x;

    // load 16x512 score rows (float4, coalesced)
    const float4* src = (const float4*)(g_scores + ((size_t)(b*LL + i0))*LL);
    float4* ps4 = (float4*)&p_s[0][0];
#pragma unroll
    for (int q = 0; q < 8; q++){
        int lin = t + q*256;
        ps4[lin] = src[lin];
    }
    __syncthreads();

    int w = t >> 5, lane = t & 31;
    // each warp handles 2 rows
#pragma unroll
    for (int rr = 0; rr < 2; ++rr){
        int r = w*2 + rr;
        float m = -1e30f;
        for (int j = lane; j < LL; j += 32) m = fmaxf(m, p_s[r][j]);
#pragma unroll
        for (int o = 16; o; o >>= 1) m = fmaxf(m, __shfl_xor_sync(0xffffffffu, m, o));
        float sum = 0.f;
        for (int j = lane; j < LL; j += 32){
            float e = __expf(p_s[r][j] - m);
            p_s[r][j] = e;
            sum += e;
        }
#pragma unroll
        for (int o = 16; o; o >>= 1) sum += __shfl_xor_sync(0xffffffffu, sum, o);
        if (lane == 0) inv_s[r] = 1.f / sum;
    }
    __syncthreads();

    // out[i,d] = inv[i] * sum_j p[i][j] * h[b,j,d]
    int d4 = t & 31;        // float4 index over D
    int ig = t >> 5;        // 0..7 -> pair of i rows
    int ia = ig * 2;
    float4 acc0 = make_float4(0.f,0.f,0.f,0.f);
    float4 acc1 = make_float4(0.f,0.f,0.f,0.f);
    const float4* hp = (const float4*)(h + (size_t)b*LL*DD) + d4;
#pragma unroll 4
    for (int j = 0; j < LL; j++){
        float4 hv = hp[(size_t)j*32];
        float pa = p_s[ia  ][j];
        float pb = p_s[ia+1][j];
        acc0.x = fmaf(pa, hv.x, acc0.x);
        acc0.y = fmaf(pa, hv.y, acc0.y);
        acc0.z = fmaf(pa, hv.z, acc0.z);
        acc0.w = fmaf(pa, hv.w, acc0.w);
        acc1.x = fmaf(pb, hv.x, acc1.x);
        acc1.y = fmaf(pb, hv.y, acc1.y);
        acc1.z = fmaf(pb, hv.z, acc1.z);
        acc1.w = fmaf(pb, hv.w, acc1.w);
    }
    float sa = inv_s[ia], sb = inv_s[ia+1];
    acc0.x *= sa; acc0.y *= sa; acc0.z *= sa; acc0.w *= sa;
    acc1.x *= sb; acc1.y *= sb; acc1.z *= sb; acc1.w *= sb;
    float4* op0 = (float4*)(out + ((size_t)(b*LL + i0 + ia    ))*DD) + d4;
    float4* op1 = (float4*)(out + ((size_t)(b*LL + i0 + ia + 1))*DD) + d4;
    op0[0] = acc0;
    op1[0] = acc1;
}

extern "C" void kernel_launch(void* const* d_in, const int* in_sizes, int n_in,
                              void* d_out, int out_size){
    const float* s = (const float*)d_in[0];
    const float* h = (const float*)d_in[1];
    const float* W = (const float*)d_in[2];
    const float* U = (const float*)d_in[3];
    const float* v = (const float*)d_in[4];
    float* out = (float*)d_out;

    proj_kernel<<<dim3(BB*LL, 2), 128>>>(s, h, W, U);
    scores_kernel<<<dim3(LL/TJ, LL/TI, BB), 256>>>(v);
    softmax_out_kernel<<<dim3(LL/16, BB), 256>>>(h, out);
}

// round 4
// speedup vs baseline: 1.2681x; 1.2681x over previous
#include <cuda_runtime.h>
#include <cuda_fp16.h>

#define BB 2
#define LL 512
#define DD 128
#define TI 16
#define TJ 64
#define TJP 65
#define TR 8          // proj rows per block

__device__ float g_sW[BB*LL*DD];
__device__ float g_hU[BB*LL*DD];
__device__ float g_scores[(size_t)BB*LL*LL];

// tanh of two fp32 via one MUFU.TANH.f16x2: returns (tanh(lo), tanh(hi))
__device__ __forceinline__ float2 tanh2_apx(float lo, float hi){
    unsigned r;
    // cvt.rn.f16x2.f32 d, a, b  ->  d.high = cvt(a), d.low = cvt(b)
    asm("{\n\t"
        ".reg .b32 t;\n\t"
        "cvt.rn.f16x2.f32 t, %1, %2;\n\t"
        "tanh.approx.f16x2 %0, t;\n\t"
        "}" : "=r"(r) : "f"(hi), "f"(lo));
    return __half22float2(*reinterpret_cast<__half2*>(&r));   // (.x=lo, .y=hi)
}

// ---------------- Kernel 0: sW = s@W, hU = h@U (8 rows / block) ----------------
__global__ void __launch_bounds__(128) proj_kernel(const float* __restrict__ s,
                                                   const float* __restrict__ h,
                                                   const float* __restrict__ W,
                                                   const float* __restrict__ U){
    __shared__ float rs[TR][DD];
    int rt    = blockIdx.x;            // row-tile 0..127
    int which = blockIdx.y;            // 0 -> sW, 1 -> hU
    const float* src = which ? h : s;
    const float* M   = which ? U : W;
    float* dst       = which ? g_hU : g_sW;
    int d = threadIdx.x;
    int row0 = rt * TR;

    // load 8 rows coalesced
#pragma unroll
    for (int q = 0; q < TR; q++)
        rs[q][d] = src[(size_t)(row0 + q)*DD + d];
    __syncthreads();

    float acc[TR];
#pragma unroll
    for (int r = 0; r < TR; r++) acc[r] = 0.f;

#pragma unroll 8
    for (int k4 = 0; k4 < DD/4; ++k4){
        // column d of M for 4 consecutive k
        float m0 = M[(k4*4+0)*DD + d];
        float m1 = M[(k4*4+1)*DD + d];
        float m2 = M[(k4*4+2)*DD + d];
        float m3 = M[(k4*4+3)*DD + d];
#pragma unroll
        for (int r = 0; r < TR; r++){
            float4 rv = ((const float4*)&rs[r][0])[k4];   // broadcast LDS.128
            acc[r] = fmaf(rv.x, m0, acc[r]);
            acc[r] = fmaf(rv.y, m1, acc[r]);
            acc[r] = fmaf(rv.z, m2, acc[r]);
            acc[r] = fmaf(rv.w, m3, acc[r]);
        }
    }
#pragma unroll
    for (int r = 0; r < TR; r++)
        dst[(size_t)(row0 + r)*DD + d] = acc[r];
}

// ---------------- Kernel 1: scores via f16x2 tanh ----------------
__global__ void __launch_bounds__(256) scores_kernel(const float* __restrict__ v){
    __shared__ float hU_t[DD][TJP];     // transposed [d][j], pad 65 -> conflict free
    __shared__ float sW_s[TI][DD];
    __shared__ float v_s[DD];

    int b  = blockIdx.z;
    int i0 = blockIdx.y * TI;
    int j0 = blockIdx.x * TJ;
    int t  = threadIdx.x;

    if (t < DD) v_s[t] = v[t];

    // sW tile (16x128) float4 coalesced
    {
        const float4* src = (const float4*)(g_sW + (size_t)(b*LL + i0)*DD);
#pragma unroll
        for (int q = 0; q < 2; q++){
            int lin = t + q*256;
            int i  = lin >> 5;
            int dv = lin & 31;
            ((float4*)&sW_s[i][0])[dv] = src[i*32 + dv];
        }
    }
    // hU tile (64x128) transposed, stride-65 conflict free
    {
        const float* src = g_hU + (size_t)(b*LL + j0)*DD;
#pragma unroll
        for (int q = 0; q < 32; q++){
            int lin = t + q*256;
            int j = lin >> 7;
            int d = lin & 127;
            hU_t[d][j] = src[j*DD + d];
        }
    }
    __syncthreads();

    int jl = t & 63;
    int ib = (t >> 6) * 4;

    float acc0=0.f, acc1=0.f, acc2=0.f, acc3=0.f;
    const float4* vv4 = (const float4*)v_s;
    const float4* w0p = (const float4*)&sW_s[ib+0][0];
    const float4* w1p = (const float4*)&sW_s[ib+1][0];
    const float4* w2p = (const float4*)&sW_s[ib+2][0];
    const float4* w3p = (const float4*)&sW_s[ib+3][0];

#pragma unroll 4
    for (int d4 = 0; d4 < 32; ++d4){
        float4 vv = vv4[d4];
        float4 w0 = w0p[d4];
        float4 w1 = w1p[d4];
        float4 w2 = w2p[d4];
        float4 w3 = w3p[d4];
        float ha = hU_t[4*d4+0][jl];
        float hb = hU_t[4*d4+1][jl];
        float hc = hU_t[4*d4+2][jl];
        float hd = hU_t[4*d4+3][jl];

        { float2 f = tanh2_apx(w0.x + ha, w0.y + hb);
          acc0 = fmaf(f.x, vv.x, acc0); acc0 = fmaf(f.y, vv.y, acc0); }
        { float2 f = tanh2_apx(w0.z + hc, w0.w + hd);
          acc0 = fmaf(f.x, vv.z, acc0); acc0 = fmaf(f.y, vv.w, acc0); }

        { float2 f = tanh2_apx(w1.x + ha, w1.y + hb);
          acc1 = fmaf(f.x, vv.x, acc1); acc1 = fmaf(f.y, vv.y, acc1); }
        { float2 f = tanh2_apx(w1.z + hc, w1.w + hd);
          acc1 = fmaf(f.x, vv.z, acc1); acc1 = fmaf(f.y, vv.w, acc1); }

        { float2 f = tanh2_apx(w2.x + ha, w2.y + hb);
          acc2 = fmaf(f.x, vv.x, acc2); acc2 = fmaf(f.y, vv.y, acc2); }
        { float2 f = tanh2_apx(w2.z + hc, w2.w + hd);
          acc2 = fmaf(f.x, vv.z, acc2); acc2 = fmaf(f.y, vv.w, acc2); }

        { float2 f = tanh2_apx(w3.x + ha, w3.y + hb);
          acc3 = fmaf(f.x, vv.x, acc3); acc3 = fmaf(f.y, vv.y, acc3); }
        { float2 f = tanh2_apx(w3.z + hc, w3.w + hd);
          acc3 = fmaf(f.x, vv.z, acc3); acc3 = fmaf(f.y, vv.w, acc3); }
    }

    float* dst = g_scores + ((size_t)(b*LL + i0 + ib))*LL + j0 + jl;
    dst[0*LL] = acc0;
    dst[1*LL] = acc1;
    dst[2*LL] = acc2;
    dst[3*LL] = acc3;
}

// ---------------- Kernel 2: softmax + out (d split in 2 halves) ----------------
__global__ void __launch_bounds__(256) softmax_out_kernel(const float* __restrict__ h,
                                                          float* __restrict__ out){
    __shared__ float p_s[16][LL];   // 32KB
    __shared__ float inv_s[16];

    int b  = blockIdx.z;
    int dh = blockIdx.y;            // 0/1 -> d half
    int i0 = blockIdx.x * 16;
    int t  = threadIdx.x;

    // load 16x512 score rows
    const float4* src = (const float4*)(g_scores + ((size_t)(b*LL + i0))*LL);
    float4* ps4 = (float4*)&p_s[0][0];
#pragma unroll
    for (int q = 0; q < 8; q++){
        int lin = t + q*256;
        ps4[lin] = src[lin];
    }
    __syncthreads();

    int w = t >> 5, lane = t & 31;
#pragma unroll
    for (int rr = 0; rr < 2; ++rr){
        int r = w*2 + rr;
        float m = -1e30f;
        for (int j = lane; j < LL; j += 32) m = fmaxf(m, p_s[r][j]);
#pragma unroll
        for (int o = 16; o; o >>= 1) m = fmaxf(m, __shfl_xor_sync(0xffffffffu, m, o));
        float sum = 0.f;
        for (int j = lane; j < LL; j += 32){
            float e = __expf(p_s[r][j] - m);
            p_s[r][j] = e;
            sum += e;
        }
#pragma unroll
        for (int o = 16; o; o >>= 1) sum += __shfl_xor_sync(0xffffffffu, sum, o);
        if (lane == 0) inv_s[r] = 1.f / sum;
    }
    __syncthreads();

    // out[i, dh*64 + 4*d4 ..] : each thread 1 row, 1 float4
    int d4 = t & 15;          // 16 float4 -> 64 floats (half of D)
    int r  = t >> 4;          // 0..15 row
    float4 acc = make_float4(0.f,0.f,0.f,0.f);
    const float4* hp = (const float4*)(h + (size_t)b*LL*DD) + dh*16 + d4;
#pragma unroll 4
    for (int j = 0; j < LL; j++){
        float4 hv = hp[(size_t)j*32];
        float p = p_s[r][j];
        acc.x = fmaf(p, hv.x, acc.x);
        acc.y = fmaf(p, hv.y, acc.y);
        acc.z = fmaf(p, hv.z, acc.z);
        acc.w = fmaf(p, hv.w, acc.w);
    }
    float sc = inv_s[r];
    acc.x *= sc; acc.y *= sc; acc.z *= sc; acc.w *= sc;
    float4* op = (float4*)(out + ((size_t)(b*LL + i0 + r))*DD) + dh*16 + d4;
    op[0] = acc;
}

extern "C" void kernel_launch(void* const* d_in, const int* in_sizes, int n_in,
                              void* d_out, int out_size){
    const float* s = (const float*)d_in[0];
    const float* h = (const float*)d_in[1];
    const float* W = (const float*)d_in[2];
    const float* U = (const float*)d_in[3];
    const float* v = (const float*)d_in[4];
    float* out = (float*)d_out;

    proj_kernel<<<dim3((BB*LL)/TR, 2), 128>>>(s, h, W, U);
    scores_kernel<<<dim3(LL/TJ, LL/TI, BB), 256>>>(v);
    softmax_out_kernel<<<dim3(LL/16, 2, BB), 256>>>(h, out);
}

// round 7
// speedup vs baseline: 1.3416x; 1.0580x over previous
#include <cuda_runtime.h>
#include <cuda_fp16.h>

#define BB 2
#define LL 512
#define DD 128
#define D2 64         // half2 pairs along d
#define TI 16
#define TJ 64
#define TJP 65
#define TR 4          // proj rows per block

__device__ float g_sW[BB*LL*DD];
__device__ float g_hU[BB*LL*DD];
__device__ float g_scores[(size_t)BB*LL*LL];

__device__ __forceinline__ __half2 h2tanh_apx(__half2 x){
    unsigned r, xi = *reinterpret_cast<unsigned*>(&x);
    asm("tanh.approx.f16x2 %0, %1;" : "=r"(r) : "r"(xi));
    return *reinterpret_cast<__half2*>(&r);
}

// ---------------- Kernel 0: sW = s@W, hU = h@U (TR rows / block) ----------------
__global__ void __launch_bounds__(128) proj_kernel(const float* __restrict__ s,
                                                   const float* __restrict__ h,
                                                   const float* __restrict__ W,
                                                   const float* __restrict__ U){
    __shared__ float rs[TR][DD];
    int rt    = blockIdx.x;            // row-tile
    int which = blockIdx.y;            // 0 -> sW, 1 -> hU
    const float* src = which ? h : s;
    const float* M   = which ? U : W;
    float* dst       = which ? g_hU : g_sW;
    int d = threadIdx.x;
    int row0 = rt * TR;

#pragma unroll
    for (int q = 0; q < TR; q++)
        rs[q][d] = src[(size_t)(row0 + q)*DD + d];
    __syncthreads();

    float acc[TR];
#pragma unroll
    for (int r = 0; r < TR; r++) acc[r] = 0.f;

#pragma unroll 8
    for (int k4 = 0; k4 < DD/4; ++k4){
        float m0 = M[(k4*4+0)*DD + d];
        float m1 = M[(k4*4+1)*DD + d];
        float m2 = M[(k4*4+2)*DD + d];
        float m3 = M[(k4*4+3)*DD + d];
#pragma unroll
        for (int r = 0; r < TR; r++){
            float4 rv = ((const float4*)&rs[r][0])[k4];   // broadcast LDS.128
            acc[r] = fmaf(rv.x, m0, acc[r]);
            acc[r] = fmaf(rv.y, m1, acc[r]);
            acc[r] = fmaf(rv.z, m2, acc[r]);
            acc[r] = fmaf(rv.w, m3, acc[r]);
        }
    }
#pragma unroll
    for (int r = 0; r < TR; r++)
        dst[(size_t)(row0 + r)*DD + d] = acc[r];
}

// ---------------- Kernel 1: scores, fully packed half2 pipeline ----------------
__global__ void __launch_bounds__(256) scores_kernel(const float* __restrict__ v){
    __shared__ __half2 hU_h2[D2][TJP];   // transposed [d2][j], pad 65 -> conflict free
    __shared__ __half2 sW_h2[TI][D2];    // [i][d2], rows 256B aligned
    __shared__ __half2 v_h2[D2];

    int b  = blockIdx.z;
    int i0 = blockIdx.y * TI;
    int j0 = blockIdx.x * TJ;
    int t  = threadIdx.x;

    // pack v
    if (t < D2){
        float2 vv = ((const float2*)v)[t];
        v_h2[t] = __floats2half2_rn(vv.x, vv.y);
    }
    // pack sW tile: 16 x 64 half2
    {
        const float2* src = (const float2*)(g_sW + (size_t)(b*LL + i0)*DD);
#pragma unroll
        for (int q = 0; q < 4; q++){
            int lin = t + q*256;          // over 1024
            int i  = lin >> 6;
            int d2 = lin & 63;
            float2 w = src[i*D2 + d2];
            sW_h2[i][d2] = __floats2half2_rn(w.x, w.y);
        }
    }
    // pack hU tile transposed: 64 x 64 half2
    {
        const float2* src = (const float2*)(g_hU + (size_t)(b*LL + j0)*DD);
#pragma unroll
        for (int q = 0; q < 16; q++){
            int lin = t + q*256;          // over 4096
            int j  = lin >> 6;
            int d2 = lin & 63;
            float2 u = src[j*D2 + d2];
            hU_h2[d2][j] = __floats2half2_rn(u.x, u.y);
        }
    }
    __syncthreads();

    int jl = t & 63;
    int ib = (t >> 6) * 4;

    float2 f0 = make_float2(0.f,0.f), f1 = f0, f2 = f0, f3 = f0;
    const __half2* w0p = &sW_h2[ib+0][0];
    const __half2* w1p = &sW_h2[ib+1][0];
    const __half2* w2p = &sW_h2[ib+2][0];
    const __half2* w3p = &sW_h2[ib+3][0];
    const __half2 hz = __floats2half2_rn(0.f, 0.f);

#pragma unroll
    for (int gg = 0; gg < 8; ++gg){       // 8 super-groups of 8 d2
        __half2 a0 = hz, a1 = hz, a2 = hz, a3 = hz;
#pragma unroll
        for (int g2 = 0; g2 < 2; ++g2){   // 2 sub-groups of 4 d2
            int g = gg*2 + g2;
            __half2 hu0 = hU_h2[4*g+0][jl];
            __half2 hu1 = hU_h2[4*g+1][jl];
            __half2 hu2 = hU_h2[4*g+2][jl];
            __half2 hu3 = hU_h2[4*g+3][jl];
            __half2 vv0 = v_h2[4*g+0];
            __half2 vv1 = v_h2[4*g+1];
            __half2 vv2 = v_h2[4*g+2];
            __half2 vv3 = v_h2[4*g+3];

            a0 = __hfma2(h2tanh_apx(__hadd2(w0p[4*g+0], hu0)), vv0, a0);
            a0 = __hfma2(h2tanh_apx(__hadd2(w0p[4*g+1], hu1)), vv1, a0);
            a0 = __hfma2(h2tanh_apx(__hadd2(w0p[4*g+2], hu2)), vv2, a0);
            a0 = __hfma2(h2tanh_apx(__hadd2(w0p[4*g+3], hu3)), vv3, a0);

            a1 = __hfma2(h2tanh_apx(__hadd2(w1p[4*g+0], hu0)), vv0, a1);
            a1 = __hfma2(h2tanh_apx(__hadd2(w1p[4*g+1], hu1)), vv1, a1);
            a1 = __hfma2(h2tanh_apx(__hadd2(w1p[4*g+2], hu2)), vv2, a1);
            a1 = __hfma2(h2tanh_apx(__hadd2(w1p[4*g+3], hu3)), vv3, a1);

            a2 = __hfma2(h2tanh_apx(__hadd2(w2p[4*g+0], hu0)), vv0, a2);
            a2 = __hfma2(h2tanh_apx(__hadd2(w2p[4*g+1], hu1)), vv1, a2);
            a2 = __hfma2(h2tanh_apx(__hadd2(w2p[4*g+2], hu2)), vv2, a2);
            a2 = __hfma2(h2tanh_apx(__hadd2(w2p[4*g+3], hu3)), vv3, a2);

            a3 = __hfma2(h2tanh_apx(__hadd2(w3p[4*g+0], hu0)), vv0, a3);
            a3 = __hfma2(h2tanh_apx(__hadd2(w3p[4*g+1], hu1)), vv1, a3);
            a3 = __hfma2(h2tanh_apx(__hadd2(w3p[4*g+2], hu2)), vv2, a3);
            a3 = __hfma2(h2tanh_apx(__hadd2(w3p[4*g+3], hu3)), vv3, a3);
        }
        // drain f16x2 accumulators into fp32
        float2 d0 = __half22float2(a0); f0.x += d0.x; f0.y += d0.y;
        float2 d1 = __half22float2(a1); f1.x += d1.x; f1.y += d1.y;
        float2 d2 = __half22float2(a2); f2.x += d2.x; f2.y += d2.y;
        float2 d3 = __half22float2(a3); f3.x += d3.x; f3.y += d3.y;
    }

    float* dst = g_scores + ((size_t)(b*LL + i0 + ib))*LL + j0 + jl;
    dst[0*LL] = f0.x + f0.y;
    dst[1*LL] = f1.x + f1.y;
    dst[2*LL] = f2.x + f2.y;
    dst[3*LL] = f3.x + f3.y;
}

// ---------------- Kernel 2: softmax + out (d split in 2 halves) ----------------
__global__ void __launch_bounds__(256) softmax_out_kernel(const float* __restrict__ h,
                                                          float* __restrict__ out){
    __shared__ float p_s[16][LL];   // 32KB
    __shared__ float inv_s[16];

    int b  = blockIdx.z;
    int dh = blockIdx.y;            // 0/1 -> d half
    int i0 = blockIdx.x * 16;
    int t  = threadIdx.x;

    const float4* src = (const float4*)(g_scores + ((size_t)(b*LL + i0))*LL);
    float4* ps4 = (float4*)&p_s[0][0];
#pragma unroll
    for (int q = 0; q < 8; q++){
        int lin = t + q*256;
        ps4[lin] = src[lin];
    }
    __syncthreads();

    int w = t >> 5, lane = t & 31;
#pragma unroll
    for (int rr = 0; rr < 2; ++rr){
        int r = w*2 + rr;
        float m = -1e30f;
        for (int j = lane; j < LL; j += 32) m = fmaxf(m, p_s[r][j]);
#pragma unroll
        for (int o = 16; o; o >>= 1) m = fmaxf(m, __shfl_xor_sync(0xffffffffu, m, o));
        float sum = 0.f;
        for (int j = lane; j < LL; j += 32){
            float e = __expf(p_s[r][j] - m);
            p_s[r][j] = e;
            sum += e;
        }
#pragma unroll
        for (int o = 16; o; o >>= 1) sum += __shfl_xor_sync(0xffffffffu, sum, o);
        if (lane == 0) inv_s[r] = 1.f / sum;
    }
    __syncthreads();

    int d4 = t & 15;          // 16 float4 -> 64 floats (half of D)
    int r  = t >> 4;          // 0..15 row
    float4 acc = make_float4(0.f,0.f,0.f,0.f);
    const float4* hp = (const float4*)(h + (size_t)b*LL*DD) + dh*16 + d4;
#pragma unroll 4
    for (int j = 0; j < LL; j++){
        float4 hv = hp[(size_t)j*32];
        float p = p_s[r][j];
        acc.x = fmaf(p, hv.x, acc.x);
        acc.y = fmaf(p, hv.y, acc.y);
        acc.z = fmaf(p, hv.z, acc.z);
        acc.w = fmaf(p, hv.w, acc.w);
    }
    float sc = inv_s[r];
    acc.x *= sc; acc.y *= sc; acc.z *= sc; acc.w *= sc;
    float4* op = (float4*)(out + ((size_t)(b*LL + i0 + r))*DD) + dh*16 + d4;
    op[0] = acc;
}

extern "C" void kernel_launch(void* const* d_in, const int* in_sizes, int n_in,
                              void* d_out, int out_size){
    const float* s = (const float*)d_in[0];
    const float* h = (const float*)d_in[1];
    const float* W = (const float*)d_in[2];
    const float* U = (const float*)d_in[3];
    const float* v = (const float*)d_in[4];
    float* out = (float*)d_out;

    proj_kernel<<<dim3((BB*LL)/TR, 2), 128>>>(s, h, W, U);
    scores_kernel<<<dim3(LL/TJ, LL/TI, BB), 256>>>(v);
    softmax_out_kernel<<<dim3(LL/16, 2, BB), 256>>>(h, out);
}

// round 12
// speedup vs baseline: 1.3600x; 1.0137x over previous
#include <cuda_runtime.h>
#include <cuda_fp16.h>

#define BB 2
#define LL 512
#define DD 128
#define D2 64         // half2 pairs along d
#define TI 16
#define TJ 64
#define TJP 65
#define TRP 4         // proj rows per block

__device__ float g_sW[BB*LL*DD];
__device__ float g_hU[BB*LL*DD];
__device__ float g_scores[(size_t)BB*LL*LL];

__device__ __forceinline__ __half2 h2tanh_apx(__half2 x){
    unsigned r, xi = *reinterpret_cast<unsigned*>(&x);
    asm("tanh.approx.f16x2 %0, %1;" : "=r"(r) : "r"(xi));
    return *reinterpret_cast<__half2*>(&r);
}

// ---- Kernel 0: sW = s@W, hU = h@U. 512 thr, 4 rows, 2-way split-K, float2 loads ----
__global__ void __launch_bounds__(512) proj_kernel(const float* __restrict__ s,
                                                   const float* __restrict__ h,
                                                   const float* __restrict__ W,
                                                   const float* __restrict__ U){
    __shared__ float  rs[TRP][DD];          // 2KB input rows
    __shared__ float2 ps[2][TRP][D2];       // 4KB split-K partials
    int rt    = blockIdx.x;
    int which = blockIdx.y;
    const float* src = which ? h : s;
    const float* M   = which ? U : W;
    float* dst       = which ? g_hU : g_sW;
    int t = threadIdx.x;
    int row0 = rt * TRP;

    // stage 4 rows (512 elements, 1 per thread)
    rs[t >> 7][t & 127] = src[(size_t)(row0 + (t >> 7))*DD + (t & 127)];
    __syncthreads();

    int d2   = t & 63;          // float2 column
    int r    = (t >> 6) & 3;    // row
    int half = t >> 8;          // k half

    const float2* M2 = (const float2*)M;
    float2 acc = make_float2(0.f, 0.f);
    int kb4 = half * 16;        // float4 k-chunk base

#pragma unroll 8
    for (int k4 = 0; k4 < 16; ++k4){
        int k = (kb4 + k4) * 4;
        float4 rv = ((const float4*)&rs[r][0])[kb4 + k4];   // LDS.128 broadcast
        float2 m0 = M2[(size_t)(k+0)*D2 + d2];
        float2 m1 = M2[(size_t)(k+1)*D2 + d2];
        float2 m2 = M2[(size_t)(k+2)*D2 + d2];
        float2 m3 = M2[(size_t)(k+3)*D2 + d2];
        acc.x = fmaf(rv.x, m0.x, acc.x);  acc.y = fmaf(rv.x, m0.y, acc.y);
        acc.x = fmaf(rv.y, m1.x, acc.x);  acc.y = fmaf(rv.y, m1.y, acc.y);
        acc.x = fmaf(rv.z, m2.x, acc.x);  acc.y = fmaf(rv.z, m2.y, acc.y);
        acc.x = fmaf(rv.w, m3.x, acc.x);  acc.y = fmaf(rv.w, m3.y, acc.y);
    }
    ps[half][r][d2] = acc;
    __syncthreads();

    if (t < 256){
        int rr = t >> 6, dd = t & 63;
        float2 a = ps[0][rr][dd], b = ps[1][rr][dd];
        float2 o = make_float2(a.x + b.x, a.y + b.y);
        ((float2*)(dst + (size_t)(row0 + rr)*DD))[dd] = o;
    }
}

// ---------------- Kernel 1: scores, packed half2 pipeline ----------------
__global__ void __launch_bounds__(256) scores_kernel(const float* __restrict__ v){
    __shared__ __half2 hU_h2[D2][TJP];
    __shared__ __half2 sW_h2[TI][D2];
    __shared__ __half2 v_h2[D2];

    int b  = blockIdx.z;
    int i0 = blockIdx.y * TI;
    int j0 = blockIdx.x * TJ;
    int t  = threadIdx.x;

    if (t < D2){
        float2 vv = ((const float2*)v)[t];
        v_h2[t] = __floats2half2_rn(vv.x, vv.y);
    }
    {
        const float2* src = (const float2*)(g_sW + (size_t)(b*LL + i0)*DD);
#pragma unroll
        for (int q = 0; q < 4; q++){
            int lin = t + q*256;
            int i  = lin >> 6;
            int d2 = lin & 63;
            float2 w = src[i*D2 + d2];
            sW_h2[i][d2] = __floats2half2_rn(w.x, w.y);
        }
    }
    {
        const float2* src = (const float2*)(g_hU + (size_t)(b*LL + j0)*DD);
#pragma unroll
        for (int q = 0; q < 16; q++){
            int lin = t + q*256;
            int j  = lin >> 6;
            int d2 = lin & 63;
            float2 u = src[j*D2 + d2];
            hU_h2[d2][j] = __floats2half2_rn(u.x, u.y);
        }
    }
    __syncthreads();

    int jl = t & 63;
    int ib = (t >> 6) * 4;

    float2 f0 = make_float2(0.f,0.f), f1 = f0, f2 = f0, f3 = f0;
    const __half2* w0p = &sW_h2[ib+0][0];
    const __half2* w1p = &sW_h2[ib+1][0];
    const __half2* w2p = &sW_h2[ib+2][0];
    const __half2* w3p = &sW_h2[ib+3][0];
    const __half2 hz = __floats2half2_rn(0.f, 0.f);

#pragma unroll
    for (int gg = 0; gg < 8; ++gg){
        __half2 a0 = hz, a1 = hz, a2 = hz, a3 = hz;
#pragma unroll
        for (int g2 = 0; g2 < 2; ++g2){
            int g = gg*2 + g2;
            __half2 hu0 = hU_h2[4*g+0][jl];
            __half2 hu1 = hU_h2[4*g+1][jl];
            __half2 hu2 = hU_h2[4*g+2][jl];
            __half2 hu3 = hU_h2[4*g+3][jl];
            __half2 vv0 = v_h2[4*g+0];
            __half2 vv1 = v_h2[4*g+1];
            __half2 vv2 = v_h2[4*g+2];
            __half2 vv3 = v_h2[4*g+3];

            a0 = __hfma2(h2tanh_apx(__hadd2(w0p[4*g+0], hu0)), vv0, a0);
            a0 = __hfma2(h2tanh_apx(__hadd2(w0p[4*g+1], hu1)), vv1, a0);
            a0 = __hfma2(h2tanh_apx(__hadd2(w0p[4*g+2], hu2)), vv2, a0);
            a0 = __hfma2(h2tanh_apx(__hadd2(w0p[4*g+3], hu3)), vv3, a0);

            a1 = __hfma2(h2tanh_apx(__hadd2(w1p[4*g+0], hu0)), vv0, a1);
            a1 = __hfma2(h2tanh_apx(__hadd2(w1p[4*g+1], hu1)), vv1, a1);
            a1 = __hfma2(h2tanh_apx(__hadd2(w1p[4*g+2], hu2)), vv2, a1);
            a1 = __hfma2(h2tanh_apx(__hadd2(w1p[4*g+3], hu3)), vv3, a1);

            a2 = __hfma2(h2tanh_apx(__hadd2(w2p[4*g+0], hu0)), vv0, a2);
            a2 = __hfma2(h2tanh_apx(__hadd2(w2p[4*g+1], hu1)), vv1, a2);
            a2 = __hfma2(h2tanh_apx(__hadd2(w2p[4*g+2], hu2)), vv2, a2);
            a2 = __hfma2(h2tanh_apx(__hadd2(w2p[4*g+3], hu3)), vv3, a2);

            a3 = __hfma2(h2tanh_apx(__hadd2(w3p[4*g+0], hu0)), vv0, a3);
            a3 = __hfma2(h2tanh_apx(__hadd2(w3p[4*g+1], hu1)), vv1, a3);
            a3 = __hfma2(h2tanh_apx(__hadd2(w3p[4*g+2], hu2)), vv2, a3);
            a3 = __hfma2(h2tanh_apx(__hadd2(w3p[4*g+3], hu3)), vv3, a3);
        }
        float2 d0 = __half22float2(a0); f0.x += d0.x; f0.y += d0.y;
        float2 d1 = __half22float2(a1); f1.x += d1.x; f1.y += d1.y;
        float2 d2 = __half22float2(a2); f2.x += d2.x; f2.y += d2.y;
        float2 d3 = __half22float2(a3); f3.x += d3.x; f3.y += d3.y;
    }

    float* dst = g_scores + ((size_t)(b*LL + i0 + ib))*LL + j0 + jl;
    dst[0*LL] = f0.x + f0.y;
    dst[1*LL] = f1.x + f1.y;
    dst[2*LL] = f2.x + f2.y;
    dst[3*LL] = f3.x + f3.y;
}

// ---------------- Kernel 2: softmax + out, j unrolled x8 for MLP ----------------
__global__ void __launch_bounds__(256) softmax_out_kernel(const float* __restrict__ h,
                                                          float* __restrict__ out){
    __shared__ float p_s[16][LL];   // 32KB
    __shared__ float inv_s[16];

    int b  = blockIdx.z;
    int dh = blockIdx.y;
    int i0 = blockIdx.x * 16;
    int t  = threadIdx.x;

    const float4* src = (const float4*)(g_scores + ((size_t)(b*LL + i0))*LL);
    float4* ps4 = (float4*)&p_s[0][0];
#pragma unroll
    for (int q = 0; q < 8; q++){
        int lin = t + q*256;
        ps4[lin] = src[lin];
    }
    __syncthreads();

    int w = t >> 5, lane = t & 31;
#pragma unroll
    for (int rr = 0; rr < 2; ++rr){
        int r = w*2 + rr;
        float m = -1e30f;
        for (int j = lane; j < LL; j += 32) m = fmaxf(m, p_s[r][j]);
#pragma unroll
        for (int o = 16; o; o >>= 1) m = fmaxf(m, __shfl_xor_sync(0xffffffffu, m, o));
        float sum = 0.f;
        for (int j = lane; j < LL; j += 32){
            float e = __expf(p_s[r][j] - m);
            p_s[r][j] = e;
            sum += e;
        }
#pragma unroll
        for (int o = 16; o; o >>= 1) sum += __shfl_xor_sync(0xffffffffu, sum, o);
        if (lane == 0) inv_s[r] = 1.f / sum;
    }
    __syncthreads();

    int d4 = t & 15;
    int r  = t >> 4;
    float4 acc = make_float4(0.f,0.f,0.f,0.f);
    const float4* hp = (const float4*)(h + (size_t)b*LL*DD) + dh*16 + d4;

    for (int j0 = 0; j0 < LL; j0 += 8){
        // 8 independent global loads in flight
        float4 h0 = hp[(size_t)(j0+0)*32];
        float4 h1 = hp[(size_t)(j0+1)*32];
        float4 h2 = hp[(size_t)(j0+2)*32];
        float4 h3 = hp[(size_t)(j0+3)*32];
        float4 h4 = hp[(size_t)(j0+4)*32];
        float4 h5 = hp[(size_t)(j0+5)*32];
        float4 h6 = hp[(size_t)(j0+6)*32];
        float4 h7 = hp[(size_t)(j0+7)*32];
        float p0 = p_s[r][j0+0], p1 = p_s[r][j0+1];
        float p2 = p_s[r][j0+2], p3 = p_s[r][j0+3];
        float p4 = p_s[r][j0+4], p5 = p_s[r][j0+5];
        float p6 = p_s[r][j0+6], p7 = p_s[r][j0+7];
        acc.x = fmaf(p0,h0.x,acc.x); acc.y = fmaf(p0,h0.y,acc.y); acc.z = fmaf(p0,h0.z,acc.z); acc.w = fmaf(p0,h0.w,acc.w);
        acc.x = fmaf(p1,h1.x,acc.x); acc.y = fmaf(p1,h1.y,acc.y); acc.z = fmaf(p1,h1.z,acc.z); acc.w = fmaf(p1,h1.w,acc.w);
        acc.x = fmaf(p2,h2.x,acc.x); acc.y = fmaf(p2,h2.y,acc.y); acc.z = fmaf(p2,h2.z,acc.z); acc.w = fmaf(p2,h2.w,acc.w);
        acc.x = fmaf(p3,h3.x,acc.x); acc.y = fmaf(p3,h3.y,acc.y); acc.z = fmaf(p3,h3.z,acc.z); acc.w = fmaf(p3,h3.w,acc.w);
        acc.x = fmaf(p4,h4.x,acc.x); acc.y = fmaf(p4,h4.y,acc.y); acc.z = fmaf(p4,h4.z,acc.z); acc.w = fmaf(p4,h4.w,acc.w);
        acc.x = fmaf(p5,h5.x,acc.x); acc.y = fmaf(p5,h5.y,acc.y); acc.z = fmaf(p5,h5.z,acc.z); acc.w = fmaf(p5,h5.w,acc.w);
        acc.x = fmaf(p6,h6.x,acc.x); acc.y = fmaf(p6,h6.y,acc.y); acc.z = fmaf(p6,h6.z,acc.z); acc.w = fmaf(p6,h6.w,acc.w);
        acc.x = fmaf(p7,h7.x,acc.x); acc.y = fmaf(p7,h7.y,acc.y); acc.z = fmaf(p7,h7.z,acc.z); acc.w = fmaf(p7,h7.w,acc.w);
    }
    float sc = inv_s[r];
    acc.x *= sc; acc.y *= sc; acc.z *= sc; acc.w *= sc;
    float4* op = (float4*)(out + ((size_t)(b*LL + i0 + r))*DD) + dh*16 + d4;
    op[0] = acc;
}

extern "C" void kernel_launch(void* const* d_in, const int* in_sizes, int n_in,
                              void* d_out, int out_size){
    const float* s = (const float*)d_in[0];
    const float* h = (const float*)d_in[1];
    const float* W = (const float*)d_in[2];
    const float* U = (const float*)d_in[3];
    const float* v = (const float*)d_in[4];
    float* out = (float*)d_out;

    proj_kernel<<<dim3((BB*LL)/TRP, 2), 512>>>(s, h, W, U);
    scores_kernel<<<dim3(LL/TJ, LL/TI, BB), 256>>>(v);
    softmax_out_kernel<<<dim3(LL/16, 2, BB), 256>>>(h, out);
}

// round 13
// speedup vs baseline: 1.4199x; 1.0441x over previous
#include <cuda_runtime.h>
#include <cuda_fp16.h>

#define BB 2
#define LL 512
#define DD 128
#define D2 64         // half2 pairs along d
#define TI 16
#define TJ 64
#define TJP 65
#define TRP 4         // proj rows per block
#define SR 8          // softmax rows per block

__device__ float g_sW[BB*LL*DD];
__device__ float g_hU[BB*LL*DD];
__device__ float g_scores[(size_t)BB*LL*LL];

__device__ __forceinline__ __half2 h2tanh_apx(__half2 x){
    unsigned r, xi = *reinterpret_cast<unsigned*>(&x);
    asm("tanh.approx.f16x2 %0, %1;" : "=r"(r) : "r"(xi));
    return *reinterpret_cast<__half2*>(&r);
}

// ---- Kernel 0: sW = s@W, hU = h@U. 512 thr, 4 rows, 4-way split-K, float4 loads ----
__global__ void __launch_bounds__(512) proj_kernel(const float* __restrict__ s,
                                                   const float* __restrict__ h,
                                                   const float* __restrict__ W,
                                                   const float* __restrict__ U){
    __shared__ float  rs[TRP][DD];          // 2KB input rows
    __shared__ float4 ps[4][TRP][32];       // 8KB split-K partials
    int rt    = blockIdx.x;
    int which = blockIdx.y;
    const float* src = which ? h : s;
    const float* M   = which ? U : W;
    float* dst       = which ? g_hU : g_sW;
    int t = threadIdx.x;
    int row0 = rt * TRP;

    // stage 4 rows (512 elements, 1 per thread)
    rs[t >> 7][t & 127] = src[(size_t)(row0 + (t >> 7))*DD + (t & 127)];
    __syncthreads();

    int d4 = t & 31;            // float4 column (32 per row)
    int r  = (t >> 5) & 3;      // row
    int q  = t >> 7;            // k quarter (0..3)

    const float4* M4 = (const float4*)M;
    float4 acc = make_float4(0.f, 0.f, 0.f, 0.f);
    int k0 = q * 32;

#pragma unroll 8
    for (int kk = 0; kk < 32; ++kk){
        int k = k0 + kk;
        float  a = rs[r][k];                  // LDS.32 broadcast (same addr per warp)
        float4 m = M4[(size_t)k*32 + d4];     // LDG.128, warp covers 512B
        acc.x = fmaf(a, m.x, acc.x);
        acc.y = fmaf(a, m.y, acc.y);
        acc.z = fmaf(a, m.z, acc.z);
        acc.w = fmaf(a, m.w, acc.w);
    }
    ps[q][r][d4] = acc;
    __syncthreads();

    if (t < 128){
        int rr = t >> 5, dd = t & 31;
        float4 a0 = ps[0][rr][dd], a1 = ps[1][rr][dd];
        float4 a2 = ps[2][rr][dd], a3 = ps[3][rr][dd];
        float4 o = make_float4((a0.x+a1.x)+(a2.x+a3.x),
                               (a0.y+a1.y)+(a2.y+a3.y),
                               (a0.z+a1.z)+(a2.z+a3.z),
                               (a0.w+a1.w)+(a2.w+a3.w));
        ((float4*)(dst + (size_t)(row0 + rr)*DD))[dd] = o;
    }
}

// ---------------- Kernel 1: scores, packed half2 pipeline (at MUFU floor) ----------------
__global__ void __launch_bounds__(256) scores_kernel(const float* __restrict__ v){
    __shared__ __half2 hU_h2[D2][TJP];
    __shared__ __half2 sW_h2[TI][D2];
    __shared__ __half2 v_h2[D2];

    int b  = blockIdx.z;
    int i0 = blockIdx.y * TI;
    int j0 = blockIdx.x * TJ;
    int t  = threadIdx.x;

    if (t < D2){
        float2 vv = ((const float2*)v)[t];
        v_h2[t] = __floats2half2_rn(vv.x, vv.y);
    }
    {
        const float2* src = (const float2*)(g_sW + (size_t)(b*LL + i0)*DD);
#pragma unroll
        for (int q = 0; q < 4; q++){
            int lin = t + q*256;
            int i  = lin >> 6;
            int d2 = lin & 63;
            float2 w = src[i*D2 + d2];
            sW_h2[i][d2] = __floats2half2_rn(w.x, w.y);
        }
    }
    {
        const float2* src = (const float2*)(g_hU + (size_t)(b*LL + j0)*DD);
#pragma unroll
        for (int q = 0; q < 16; q++){
            int lin = t + q*256;
            int j  = lin >> 6;
            int d2 = lin & 63;
            float2 u = src[j*D2 + d2];
            hU_h2[d2][j] = __floats2half2_rn(u.x, u.y);
        }
    }
    __syncthreads();

    int jl = t & 63;
    int ib = (t >> 6) * 4;

    float2 f0 = make_float2(0.f,0.f), f1 = f0, f2 = f0, f3 = f0;
    const __half2* w0p = &sW_h2[ib+0][0];
    const __half2* w1p = &sW_h2[ib+1][0];
    const __half2* w2p = &sW_h2[ib+2][0];
    const __half2* w3p = &sW_h2[ib+3][0];
    const __half2 hz = __floats2half2_rn(0.f, 0.f);

#pragma unroll
    for (int gg = 0; gg < 8; ++gg){
        __half2 a0 = hz, a1 = hz, a2 = hz, a3 = hz;
#pragma unroll
        for (int g2 = 0; g2 < 2; ++g2){
            int g = gg*2 + g2;
            __half2 hu0 = hU_h2[4*g+0][jl];
            __half2 hu1 = hU_h2[4*g+1][jl];
            __half2 hu2 = hU_h2[4*g+2][jl];
            __half2 hu3 = hU_h2[4*g+3][jl];
            __half2 vv0 = v_h2[4*g+0];
            __half2 vv1 = v_h2[4*g+1];
            __half2 vv2 = v_h2[4*g+2];
            __half2 vv3 = v_h2[4*g+3];

            a0 = __hfma2(h2tanh_apx(__hadd2(w0p[4*g+0], hu0)), vv0, a0);
            a0 = __hfma2(h2tanh_apx(__hadd2(w0p[4*g+1], hu1)), vv1, a0);
            a0 = __hfma2(h2tanh_apx(__hadd2(w0p[4*g+2], hu2)), vv2, a0);
            a0 = __hfma2(h2tanh_apx(__hadd2(w0p[4*g+3], hu3)), vv3, a0);

            a1 = __hfma2(h2tanh_apx(__hadd2(w1p[4*g+0], hu0)), vv0, a1);
            a1 = __hfma2(h2tanh_apx(__hadd2(w1p[4*g+1], hu1)), vv1, a1);
            a1 = __hfma2(h2tanh_apx(__hadd2(w1p[4*g+2], hu2)), vv2, a1);
            a1 = __hfma2(h2tanh_apx(__hadd2(w1p[4*g+3], hu3)), vv3, a1);

            a2 = __hfma2(h2tanh_apx(__hadd2(w2p[4*g+0], hu0)), vv0, a2);
            a2 = __hfma2(h2tanh_apx(__hadd2(w2p[4*g+1], hu1)), vv1, a2);
            a2 = __hfma2(h2tanh_apx(__hadd2(w2p[4*g+2], hu2)), vv2, a2);
            a2 = __hfma2(h2tanh_apx(__hadd2(w2p[4*g+3], hu3)), vv3, a2);

            a3 = __hfma2(h2tanh_apx(__hadd2(w3p[4*g+0], hu0)), vv0, a3);
            a3 = __hfma2(h2tanh_apx(__hadd2(w3p[4*g+1], hu1)), vv1, a3);
            a3 = __hfma2(h2tanh_apx(__hadd2(w3p[4*g+2], hu2)), vv2, a3);
            a3 = __hfma2(h2tanh_apx(__hadd2(w3p[4*g+3], hu3)), vv3, a3);
        }
        float2 d0 = __half22float2(a0); f0.x += d0.x; f0.y += d0.y;
        float2 d1 = __half22float2(a1); f1.x += d1.x; f1.y += d1.y;
        float2 d2 = __half22float2(a2); f2.x += d2.x; f2.y += d2.y;
        float2 d3 = __half22float2(a3); f3.x += d3.x; f3.y += d3.y;
    }

    float* dst = g_scores + ((size_t)(b*LL + i0 + ib))*LL + j0 + jl;
    dst[0*LL] = f0.x + f0.y;
    dst[1*LL] = f1.x + f1.y;
    dst[2*LL] = f2.x + f2.y;
    dst[3*LL] = f3.x + f3.y;
}

// ------ Kernel 2: softmax + out. 8 rows/block, full D, 2-way j-split, 512 thr ------
__global__ void __launch_bounds__(512) softmax_out_kernel(const float* __restrict__ h,
                                                          float* __restrict__ out){
    __shared__ float  p_s[SR][LL];        // 16KB exp'd scores
    __shared__ float  inv_s[SR];
    __shared__ float4 ps[2][SR][32];      // 8KB j-split partials

    int b  = blockIdx.y;
    int i0 = blockIdx.x * SR;
    int t  = threadIdx.x;

    // load 8x512 score rows (1024 float4 over 512 threads)
    const float4* src = (const float4*)(g_scores + ((size_t)(b*LL + i0))*LL);
    float4* ps4 = (float4*)&p_s[0][0];
    ps4[t]       = src[t];
    ps4[t + 512] = src[t + 512];
    __syncthreads();

    int w = t >> 5, lane = t & 31;
    if (w < SR){
        int r = w;
        float m = -1e30f;
#pragma unroll
        for (int j = lane; j < LL; j += 32) m = fmaxf(m, p_s[r][j]);
#pragma unroll
        for (int o = 16; o; o >>= 1) m = fmaxf(m, __shfl_xor_sync(0xffffffffu, m, o));
        float sum = 0.f;
#pragma unroll
        for (int j = lane; j < LL; j += 32){
            float e = __expf(p_s[r][j] - m);
            p_s[r][j] = e;
            sum += e;
        }
#pragma unroll
        for (int o = 16; o; o >>= 1) sum += __shfl_xor_sync(0xffffffffu, sum, o);
        if (lane == 0) inv_s[r] = 1.f / sum;
    }
    __syncthreads();

    // AV: thread = (d4: 32) x (row: 8) x (jchunk: 2)
    int d4 = t & 31;
    int r  = (t >> 5) & 7;
    int jc = t >> 8;             // 0/1
    const float4* hp = (const float4*)(h + (size_t)b*LL*DD) + d4;
    float4 acc = make_float4(0.f,0.f,0.f,0.f);
    int jbeg = jc * 256;

#pragma unroll 4
    for (int j = jbeg; j < jbeg + 256; ++j){
        float4 hv = hp[(size_t)j*32];
        float p = p_s[r][j];
        acc.x = fmaf(p, hv.x, acc.x);
        acc.y = fmaf(p, hv.y, acc.y);
        acc.z = fmaf(p, hv.z, acc.z);
        acc.w = fmaf(p, hv.w, acc.w);
    }
    ps[jc][r][d4] = acc;
    __syncthreads();

    if (t < 256){
        int rr = t >> 5, dd = t & 31;
        float4 a = ps[0][rr][dd], c = ps[1][rr][dd];
        float sc = inv_s[rr];
        float4 o = make_float4((a.x+c.x)*sc, (a.y+c.y)*sc,
                               (a.z+c.z)*sc, (a.w+c.w)*sc);
        ((float4*)(out + ((size_t)(b*LL + i0 + rr))*DD))[dd] = o;
    }
}

extern "C" void kernel_launch(void* const* d_in, const int* in_sizes, int n_in,
                              void* d_out, int out_size){
    const float* s = (const float*)d_in[0];
    const float* h = (const float*)d_in[1];
    const float* W = (const float*)d_in[2];
    const float* U = (const float*)d_in[3];
    const float* v = (const float*)d_in[4];
    float* out = (float*)d_out;

    proj_kernel<<<dim3((BB*LL)/TRP, 2), 512>>>(s, h, W, U);
    scores_kernel<<<dim3(LL/TJ, LL/TI, BB), 256>>>(v);
    softmax_out_kernel<<<dim3(LL/SR, BB), 512>>>(h, out);
}

// round 16
// speedup vs baseline: 2.1594x; 1.5208x over previous
#include <cuda_runtime.h>
#include <cuda_fp16.h>

#define BB 2
#define LL 512
#define DD 128
#define D2 64         // half2 pairs along d
#define TI 16
#define TJ 64
#define TJP 65
#define PRT 16        // proj rows per block
#define SR 8          // softmax rows per block

__device__ unsigned g_sW_h2[BB*LL*D2];   // half2-packed sW
__device__ unsigned g_hU_h2[BB*LL*D2];   // half2-packed hU
__device__ float    g_scores[(size_t)BB*LL*LL];

__device__ __forceinline__ __half2 h2tanh_apx(__half2 x){
    unsigned r, xi = *reinterpret_cast<unsigned*>(&x);
    asm("tanh.approx.f16x2 %0, %1;" : "=r"(r) : "r"(xi));
    return *reinterpret_cast<__half2*>(&r);
}
__device__ __forceinline__ unsigned pack_h2(float lo, float hi){
    __half2 hh = __floats2half2_rn(lo, hi);
    return *reinterpret_cast<unsigned*>(&hh);
}

// ---- Kernel 0: sW = s@W, hU = h@U. 256 thr, 16 rows, M smem-staged, 2-row reg blocking ----
__global__ void __launch_bounds__(256) proj_kernel(const float* __restrict__ s,
                                                   const float* __restrict__ h,
                                                   const float* __restrict__ W,
                                                   const float* __restrict__ U){
    __shared__ float M_s[64][DD];     // 32KB k-tile of weights
    __shared__ float rs_t[DD][PRT];   // 8KB transposed input rows
    int rt    = blockIdx.x;
    int which = blockIdx.y;
    const float* src = which ? h : s;
    const float* M   = which ? U : W;
    unsigned* dst    = which ? g_hU_h2 : g_sW_h2;
    int t = threadIdx.x;
    int row0 = rt * PRT;

    // load 16 rows transposed (coalesced float4 reads, scattered smem writes)
    {
        const float4* sp = (const float4*)(src + (size_t)row0*DD);
#pragma unroll
        for (int q = 0; q < 2; q++){
            int idx = t + q*256;        // over 512 float4
            int row = idx >> 5;         // 32 float4 per row (FIXED)
            int k4  = idx & 31;
            float4 v4 = sp[idx];
            rs_t[k4*4+0][row] = v4.x;
            rs_t[k4*4+1][row] = v4.y;
            rs_t[k4*4+2][row] = v4.z;
            rs_t[k4*4+3][row] = v4.w;
        }
    }

    int d4 = t & 31;     // float4 column of M
    int rg = t >> 5;     // 0..7 -> rows 2rg, 2rg+1
    float4 acc0 = make_float4(0.f,0.f,0.f,0.f);
    float4 acc1 = make_float4(0.f,0.f,0.f,0.f);

    for (int kt = 0; kt < 2; ++kt){
        __syncthreads();
        // stage M k-tile 64x128 (coalesced copy)
        const float4* mp = (const float4*)(M + (size_t)kt*64*DD);
        float4* md = (float4*)&M_s[0][0];
#pragma unroll
        for (int q = 0; q < 8; q++) md[t + q*256] = mp[t + q*256];
        __syncthreads();

#pragma unroll 4
        for (int kk = 0; kk < 64; ++kk){
            float4 m = ((const float4*)&M_s[kk][0])[d4];
            float2 a = *(const float2*)&rs_t[kt*64 + kk][rg*2];   // broadcast
            acc0.x = fmaf(a.x, m.x, acc0.x);
            acc0.y = fmaf(a.x, m.y, acc0.y);
            acc0.z = fmaf(a.x, m.z, acc0.z);
            acc0.w = fmaf(a.x, m.w, acc0.w);
            acc1.x = fmaf(a.y, m.x, acc1.x);
            acc1.y = fmaf(a.y, m.y, acc1.y);
            acc1.z = fmaf(a.y, m.z, acc1.z);
            acc1.w = fmaf(a.y, m.w, acc1.w);
        }
    }

    // store half2-packed (uint2 per row)
    unsigned* dp = dst + (size_t)(row0 + rg*2)*D2 + d4*2;
    uint2 u0, u1;
    u0.x = pack_h2(acc0.x, acc0.y);  u0.y = pack_h2(acc0.z, acc0.w);
    u1.x = pack_h2(acc1.x, acc1.y);  u1.y = pack_h2(acc1.z, acc1.w);
    *(uint2*)dp        = u0;
    *(uint2*)(dp + D2) = u1;
}

// ---------------- Kernel 1: scores, packed half2 pipeline (at MUFU floor) ----------------
__global__ void __launch_bounds__(256) scores_kernel(const float* __restrict__ v){
    __shared__ __half2 hU_h2[D2][TJP];
    __shared__ __half2 sW_h2[TI][D2];
    __shared__ __half2 v_h2[D2];

    int b  = blockIdx.z;
    int i0 = blockIdx.y * TI;
    int j0 = blockIdx.x * TJ;
    int t  = threadIdx.x;

    if (t < D2){
        float2 vv = ((const float2*)v)[t];
        v_h2[t] = __floats2half2_rn(vv.x, vv.y);
    }
    {   // sW tile: 512 uint2, direct copy
        const uint2* srcw = (const uint2*)(g_sW_h2 + (size_t)(b*LL + i0)*D2);
#pragma unroll
        for (int q = 0; q < 2; q++){
            int lin = t + q*256;
            int i  = lin >> 5;
            int du = lin & 31;
            ((uint2*)&sW_h2[i][0])[du] = srcw[lin];
        }
    }
    {   // hU tile transposed: 4096 uint scalar
        const unsigned* srcu = g_hU_h2 + (size_t)(b*LL + j0)*D2;
#pragma unroll
        for (int q = 0; q < 16; q++){
            int lin = t + q*256;
            int j  = lin >> 6;
            int d2 = lin & 63;
            *(unsigned*)&hU_h2[d2][j] = srcu[lin];
        }
    }
    __syncthreads();

    int jl = t & 63;
    int ib = (t >> 6) * 4;

    float2 f0 = make_float2(0.f,0.f), f1 = f0, f2 = f0, f3 = f0;
    const __half2* w0p = &sW_h2[ib+0][0];
    const __half2* w1p = &sW_h2[ib+1][0];
    const __half2* w2p = &sW_h2[ib+2][0];
    const __half2* w3p = &sW_h2[ib+3][0];
    const __half2 hz = __floats2half2_rn(0.f, 0.f);

#pragma unroll
    for (int gg = 0; gg < 8; ++gg){
        __half2 a0 = hz, a1 = hz, a2 = hz, a3 = hz;
#pragma unroll
        for (int g2 = 0; g2 < 2; ++g2){
            int g = gg*2 + g2;
            __half2 hu0 = hU_h2[4*g+0][jl];
            __half2 hu1 = hU_h2[4*g+1][jl];
            __half2 hu2 = hU_h2[4*g+2][jl];
            __half2 hu3 = hU_h2[4*g+3][jl];
            __half2 vv0 = v_h2[4*g+0];
            __half2 vv1 = v_h2[4*g+1];
            __half2 vv2 = v_h2[4*g+2];
            __half2 vv3 = v_h2[4*g+3];

            a0 = __hfma2(h2tanh_apx(__hadd2(w0p[4*g+0], hu0)), vv0, a0);
            a0 = __hfma2(h2tanh_apx(__hadd2(w0p[4*g+1], hu1)), vv1, a0);
            a0 = __hfma2(h2tanh_apx(__hadd2(w0p[4*g+2], hu2)), vv2, a0);
            a0 = __hfma2(h2tanh_apx(__hadd2(w0p[4*g+3], hu3)), vv3, a0);

            a1 = __hfma2(h2tanh_apx(__hadd2(w1p[4*g+0], hu0)), vv0, a1);
            a1 = __hfma2(h2tanh_apx(__hadd2(w1p[4*g+1], hu1)), vv1, a1);
            a1 = __hfma2(h2tanh_apx(__hadd2(w1p[4*g+2], hu2)), vv2, a1);
            a1 = __hfma2(h2tanh_apx(__hadd2(w1p[4*g+3], hu3)), vv3, a1);

            a2 = __hfma2(h2tanh_apx(__hadd2(w2p[4*g+0], hu0)), vv0, a2);
            a2 = __hfma2(h2tanh_apx(__hadd2(w2p[4*g+1], hu1)), vv1, a2);
            a2 = __hfma2(h2tanh_apx(__hadd2(w2p[4*g+2], hu2)), vv2, a2);
            a2 = __hfma2(h2tanh_apx(__hadd2(w2p[4*g+3], hu3)), vv3, a2);

            a3 = __hfma2(h2tanh_apx(__hadd2(w3p[4*g+0], hu0)), vv0, a3);
            a3 = __hfma2(h2tanh_apx(__hadd2(w3p[4*g+1], hu1)), vv1, a3);
            a3 = __hfma2(h2tanh_apx(__hadd2(w3p[4*g+2], hu2)), vv2, a3);
            a3 = __hfma2(h2tanh_apx(__hadd2(w3p[4*g+3], hu3)), vv3, a3);
        }
        float2 d0 = __half22float2(a0); f0.x += d0.x; f0.y += d0.y;
        float2 d1 = __half22float2(a1); f1.x += d1.x; f1.y += d1.y;
        float2 d2 = __half22float2(a2); f2.x += d2.x; f2.y += d2.y;
        float2 d3 = __half22float2(a3); f3.x += d3.x; f3.y += d3.y;
    }

    float* dst = g_scores + ((size_t)(b*LL + i0 + ib))*LL + j0 + jl;
    dst[0*LL] = f0.x + f0.y;
    dst[1*LL] = f1.x + f1.y;
    dst[2*LL] = f2.x + f2.y;
    dst[3*LL] = f3.x + f3.y;
}

// ------ Kernel 2: softmax + out. 8 rows/block, all-rows register blocking ------
__global__ void __launch_bounds__(512) softmax_out_kernel(const float* __restrict__ h,
                                                          float* __restrict__ out){
    __shared__ union SMU {
        struct { float p_s[SR][LL]; float p_t[LL][SR]; } a;  // 16KB + 16KB
        float4 part[8][SR][32];                              // 32KB (used after AV loop)
    } sm;
    __shared__ float inv_s[SR];

    int b  = blockIdx.y;
    int i0 = blockIdx.x * SR;
    int t  = threadIdx.x;

    // load 8x512 score rows
    const float4* src = (const float4*)(g_scores + ((size_t)(b*LL + i0))*LL);
    float4* ps4 = (float4*)&sm.a.p_s[0][0];
    ps4[t]       = src[t];
    ps4[t + 512] = src[t + 512];
    __syncthreads();

    int w = t >> 5, lane = t & 31;
    if (w < SR){
        int r = w;
        float m = -1e30f;
#pragma unroll
        for (int q = 0; q < 16; q++) m = fmaxf(m, sm.a.p_s[r][lane + q*32]);
#pragma unroll
        for (int o = 16; o; o >>= 1) m = fmaxf(m, __shfl_xor_sync(0xffffffffu, m, o));
        float sum = 0.f;
#pragma unroll
        for (int q = 0; q < 16; q++){
            int j = lane + q*32;
            float e = __expf(sm.a.p_s[r][j] - m);
            sm.a.p_t[j][r] = e;                 // transposed for AV
            sum += e;
        }
#pragma unroll
        for (int o = 16; o; o >>= 1) sum += __shfl_xor_sync(0xffffffffu, sum, o);
        if (lane == 0) inv_s[r] = 1.f / sum;
    }
    __syncthreads();

    // AV: thread = (d4:32) x (jc:16); each thread accumulates ALL 8 rows
    int d4 = t & 31;
    int jc = t >> 5;
    float4 acc[SR];
#pragma unroll
    for (int r = 0; r < SR; r++) acc[r] = make_float4(0.f,0.f,0.f,0.f);
    const float4* hp = (const float4*)(h + (size_t)b*LL*DD) + d4;
    int jbeg = jc * 32;

#pragma unroll 4
    for (int jj = 0; jj < 32; ++jj){
        int j = jbeg + jj;
        float4 hv = hp[(size_t)j*32];                          // feeds 32 FMA
        float4 p0 = *(const float4*)&sm.a.p_t[j][0];           // broadcast
        float4 p1 = *(const float4*)&sm.a.p_t[j][4];           // broadcast
        acc[0].x = fmaf(p0.x, hv.x, acc[0].x); acc[0].y = fmaf(p0.x, hv.y, acc[0].y);
        acc[0].z = fmaf(p0.x, hv.z, acc[0].z); acc[0].w = fmaf(p0.x, hv.w, acc[0].w);
        acc[1].x = fmaf(p0.y, hv.x, acc[1].x); acc[1].y = fmaf(p0.y, hv.y, acc[1].y);
        acc[1].z = fmaf(p0.y, hv.z, acc[1].z); acc[1].w = fmaf(p0.y, hv.w, acc[1].w);
        acc[2].x = fmaf(p0.z, hv.x, acc[2].x); acc[2].y = fmaf(p0.z, hv.y, acc[2].y);
        acc[2].z = fmaf(p0.z, hv.z, acc[2].z); acc[2].w = fmaf(p0.z, hv.w, acc[2].w);
        acc[3].x = fmaf(p0.w, hv.x, acc[3].x); acc[3].y = fmaf(p0.w, hv.y, acc[3].y);
        acc[3].z = fmaf(p0.w, hv.z, acc[3].z); acc[3].w = fmaf(p0.w, hv.w, acc[3].w);
        acc[4].x = fmaf(p1.x, hv.x, acc[4].x); acc[4].y = fmaf(p1.x, hv.y, acc[4].y);
        acc[4].z = fmaf(p1.x, hv.z, acc[4].z); acc[4].w = fmaf(p1.x, hv.w, acc[4].w);
        acc[5].x = fmaf(p1.y, hv.x, acc[5].x); acc[5].y = fmaf(p1.y, hv.y, acc[5].y);
        acc[5].z = fmaf(p1.y, hv.z, acc[5].z); acc[5].w = fmaf(p1.y, hv.w, acc[5].w);
        acc[6].x = fmaf(p1.z, hv.x, acc[6].x); acc[6].y = fmaf(p1.z, hv.y, acc[6].y);
        acc[6].z = fmaf(p1.z, hv.z, acc[6].z); acc[6].w = fmaf(p1.z, hv.w, acc[6].w);
        acc[7].x = fmaf(p1.w, hv.x, acc[7].x); acc[7].y = fmaf(p1.w, hv.y, acc[7].y);
        acc[7].z = fmaf(p1.w, hv.z, acc[7].z); acc[7].w = fmaf(p1.w, hv.w, acc[7].w);
    }
    __syncthreads();   // p_s/p_t dead; union region reused for partials

    if (jc >= 8){
#pragma unroll
        for (int r = 0; r < SR; r++) sm.part[jc-8][r][d4] = acc[r];
    }
    __syncthreads();
    if (jc < 8){
#pragma unroll
        for (int r = 0; r < SR; r++){
            float4 q = sm.part[jc][r][d4];
            acc[r].x += q.x; acc[r].y += q.y; acc[r].z += q.z; acc[r].w += q.w;
        }
    }
    __syncthreads();
    if (jc < 8){
#pragma unroll
        for (int r = 0; r < SR; r++) sm.part[jc][r][d4] = acc[r];
    }
    __syncthreads();

    if (t < 256){
        int rr = t >> 5, dd = t & 31;
        float4 o = make_float4(0.f,0.f,0.f,0.f);
#pragma unroll
        for (int q = 0; q < 8; q++){
            float4 p = sm.part[q][rr][dd];
            o.x += p.x; o.y += p.y; o.z += p.z; o.w += p.w;
        }
        float sc = inv_s[rr];
        o.x *= sc; o.y *= sc; o.z *= sc; o.w *= sc;
        ((float4*)(out + ((size_t)(b*LL + i0 + rr))*DD))[dd] = o;
    }
}

extern "C" void kernel_launch(void* const* d_in, const int* in_sizes, int n_in,
                              void* d_out, int out_size){
    const float* s = (const float*)d_in[0];
    const float* h = (const float*)d_in[1];
    const float* W = (const float*)d_in[2];
    const float* U = (const float*)d_in[3];
    const float* v = (const float*)d_in[4];
    float* out = (float*)d_out;

    proj_kernel<<<dim3((BB*LL)/PRT, 2), 256>>>(s, h, W, U);
    scores_kernel<<<dim3(LL/TJ, LL/TI, BB), 256>>>(v);
    softmax_out_kernel<<<dim3(LL/SR, BB), 512>>>(h, out);
}